// round 5
// baseline (speedup 1.0000x reference)
#include <cuda_runtime.h>
#include <cstdint>

// x: [2][4][8][8][8][96][96] f32, W: [9][4][4][3][3][3] f32, b: [9][4] f32
// out: [2][4][6][6][8][96][96] f32
#define HW_PLANE 9216
#define TSTRIDE  104            // floats per tile row
#define TSZ      (34 * TSTRIDE) // floats per buffer
typedef unsigned long long u64;

__device__ __forceinline__ void cp_async16(uint32_t saddr, const void* g, int srcsize) {
    asm volatile("cp.async.cg.shared.global [%0], [%1], 16, %2;\n"
                 :: "r"(saddr), "l"(g), "r"(srcsize));
}
__device__ __forceinline__ void cp_commit() {
    asm volatile("cp.async.commit_group;\n" ::: "memory");
}
__device__ __forceinline__ void cp_wait1() {
    asm volatile("cp.async.wait_group 1;\n" ::: "memory");
}
__device__ __forceinline__ u64 pack2(float lo, float hi) {
    u64 r; asm("mov.b64 %0, {%1, %2};" : "=l"(r) : "f"(lo), "f"(hi)); return r;
}
__device__ __forceinline__ void ffma2(u64& a, u64 x, u64 w) {
    asm("fma.rn.f32x2 %0, %1, %2, %0;" : "+l"(a) : "l"(x), "l"(w));
}
__device__ __forceinline__ float2 unpack2(u64 v) {
    float lo, hi; asm("mov.b64 {%0, %1}, %2;" : "=f"(lo), "=f"(hi) : "l"(v));
    return make_float2(lo, hi);
}

// Block: 384 threads = 24 tx (4 cols) x 16 ty (2 rows). Tile 32 rows x 96 cols, 4 o-chans.
// 108 iters = ci(4) x ij(9) x kd(3). 6 smem buffers, 2 iters/phase (54 barriers),
// kh-blocked rolling-window compute, cross-barrier weight preload, f32x2 FMAs. 2 blocks/SM.
__global__ __launch_bounds__(384, 2)
void conv5d_kernel(const float* __restrict__ x,
                   const float* __restrict__ Wg,
                   const float* __restrict__ bg,
                   float* __restrict__ out)
{
    extern __shared__ __align__(16) float tiles[];     // [6][TSZ]
    __shared__ __align__(16) float wsh[3888];          // [n(108)][tap(9)][o(4)]
    __shared__ float mbsh[4];

    const int tid   = threadIdx.x;
    const int htile = blockIdx.x % 3;
    const int d     = blockIdx.x / 3;
    const int t     = blockIdx.y;
    const int c     = blockIdx.z % 6;
    const int b     = blockIdx.z / 6;
    const int h0    = htile * 32;

    // ---- stage weights: wsh[n*36 + tap*4 + o], n = (ci*9+ij)*3+kd
    for (int idx = tid; idx < 3888; idx += 384) {
        int o   = idx & 3;
        int tap = (idx >> 2) % 9;
        int kd  = (idx / 36) % 3;
        int ij  = (idx / 108) % 9;
        int ci  = idx / 972;
        int kh = tap / 3, kw = tap - kh * 3;
        wsh[idx] = Wg[((ij * 4 + o) * 4 + ci) * 27 + kd * 9 + kh * 3 + kw];
    }
    if (tid < 4) {
        float s = 0.f;
        #pragma unroll
        for (int ij = 0; ij < 9; ij++) s += bg[ij * 4 + tid];
        mbsh[tid] = s * (1.0f / 9.0f);
    }
    // halo columns (w=-1, w=96) are conv zero-padding: zero once, never loaded
    if (tid < 204) {  // 6 bufs x 34 rows
        int buf = tid / 34, row = tid - buf * 34;
        tiles[buf * TSZ + row * TSTRIDE + 3]   = 0.f;
        tiles[buf * TSZ + row * TSTRIDE + 100] = 0.f;
    }

    // ---- per-thread interior load slots (16B each): 34 rows x 24 quads = 816
    int   mso[3];     // smem float offset, -1 unused
    int   mgo[3];     // global plane offset
    int   msz[3];     // 16 if h valid else 0
    #pragma unroll
    for (int e = 0; e < 3; e++) {
        int idx = tid + e * 384;
        if (idx < 816) {
            int row = idx / 24;
            int q   = idx - row * 24;
            int h   = h0 - 1 + row;
            bool hv = (h >= 0 && h < 96);
            mso[e] = row * TSTRIDE + 4 + q * 4;
            mgo[e] = (hv ? h : 0) * 96 + q * 4;
            msz[e] = hv ? 16 : 0;
        } else {
            mso[e] = -1;
        }
    }

    uint32_t sb[6];
    #pragma unroll
    for (int k = 0; k < 6; k++)
        sb[k] = (uint32_t)__cvta_generic_to_shared(tiles + k * TSZ);

    // ---- issue-side state machine over (ci, i, j, kd)
    const float* xb = x + (size_t)b * (4 * 8 * 8 * 8 * HW_PLANE);
    const float* bcur = xb + ((size_t)((c * 8 + t) * 8) + (d - 1)) * HW_PLANE;
    int kd_m = 0, jj = 0, ii = 0;
    const bool dval0 = (d >= 1), dval2 = (d <= 6);

    auto issue_buf = [&](uint32_t sbase) {
        bool dv = (kd_m == 0) ? dval0 : ((kd_m == 2) ? dval2 : true);
        const float* plane = dv ? (bcur + (size_t)kd_m * HW_PLANE) : (bcur + HW_PLANE);
        #pragma unroll
        for (int e = 0; e < 3; e++) {
            if (mso[e] >= 0)
                cp_async16(sbase + (uint32_t)mso[e] * 4u, plane + mgo[e], dv ? msz[e] : 0);
        }
        kd_m++;
        if (kd_m == 3) {
            kd_m = 0;
            long step = 8;                      // j++
            jj++;
            if (jj == 3) { jj = 0; ii++; step = 48;          // i++
                if (ii == 3) { ii = 0; step = 368; } }       // ci++
            bcur += step * (long)HW_PLANE;
        }
    };

    // accumulators: (o0,o1) and (o2,o3) pairs, [py][px]
    u64 a01[2][4], a23[2][4];
    #pragma unroll
    for (int py = 0; py < 2; py++)
        #pragma unroll
        for (int px = 0; px < 4; px++) { a01[py][px] = 0ull; a23[py][px] = 0ull; }

    const int tx = tid % 24;
    const int ty = tid / 24;
    const int rowbase = ty * 2 * TSTRIDE + tx * 4;

    // load one tile row -> 6 duplicated f32x2 values
    auto loadrow = [&](const float* rw, u64* p) {
        float  lv = rw[3];
        float4 m  = *reinterpret_cast<const float4*>(rw + 4);
        float  rv = rw[8];
        p[0] = pack2(lv,  lv);
        p[1] = pack2(m.x, m.x);
        p[2] = pack2(m.y, m.y);
        p[3] = pack2(m.z, m.z);
        p[4] = pack2(m.w, m.w);
        p[5] = pack2(rv,  rv);
    };
    // one kh row of taps (3 kw) applied to two output rows (py0 from p0, py1 from p1)
    auto fmakh = [&](const u64* p0, const u64* p1,
                     ulonglong2 w0, ulonglong2 w1, ulonglong2 w2) {
        #pragma unroll
        for (int px = 0; px < 4; px++) {
            ffma2(a01[0][px], p0[px],     w0.x); ffma2(a23[0][px], p0[px],     w0.y);
            ffma2(a01[1][px], p1[px],     w0.x); ffma2(a23[1][px], p1[px],     w0.y);
            ffma2(a01[0][px], p0[px + 1], w1.x); ffma2(a23[0][px], p0[px + 1], w1.y);
            ffma2(a01[1][px], p1[px + 1], w1.x); ffma2(a23[1][px], p1[px + 1], w1.y);
            ffma2(a01[0][px], p0[px + 2], w2.x); ffma2(a23[0][px], p0[px + 2], w2.y);
            ffma2(a01[1][px], p1[px + 2], w2.x); ffma2(a23[1][px], p1[px + 2], w2.y);
        }
    };
    // one iteration, kh-blocked rolling window; kh=0 weights passed in (preloadable)
    auto compute_iter = [&](int n, const float* tb,
                            ulonglong2 w0, ulonglong2 w1, ulonglong2 w2) {
        const ulonglong2* wb = reinterpret_cast<const ulonglong2*>(&wsh[n * 36]);
        u64 pa[6], pb[6];
        loadrow(tb,               pa);     // row 0
        loadrow(tb + TSTRIDE,     pb);     // row 1
        fmakh(pa, pb, w0, w1, w2);         // kh = 0
        loadrow(tb + 2 * TSTRIDE, pa);     // row 2 replaces row 0
        fmakh(pb, pa, wb[3], wb[4], wb[5]);// kh = 1
        loadrow(tb + 3 * TSTRIDE, pb);     // row 3 replaces row 1
        fmakh(pa, pb, wb[6], wb[7], wb[8]);// kh = 2
    };

    // prologue: 2 groups (2 bufs each) in flight
    issue_buf(sb[0]); issue_buf(sb[1]); cp_commit();
    issue_buf(sb[2]); issue_buf(sb[3]); cp_commit();

    // 54 phases x 2 iters; buffer pattern repeats every 3 phases -> unroll 3
    #pragma unroll 3
    for (int p = 0; p < 54; p++) {
        const int n0 = 2 * p;

        // cross-barrier preload: kh=0 weights of iter n0 (independent of cp.async data)
        const ulonglong2* wbA = reinterpret_cast<const ulonglong2*>(&wsh[n0 * 36]);
        ulonglong2 wA0 = wbA[0], wA1 = wbA[1], wA2 = wbA[2];

        cp_wait1();              // all but newest group done -> iters n0, n0+1 arrived
        __syncthreads();         // visible to all; bufs (n0+4)%6,(n0+5)%6 no longer read

        if (n0 + 4 < 108) issue_buf(sb[(n0 + 4) % 6]);
        if (n0 + 5 < 108) issue_buf(sb[(n0 + 5) % 6]);
        cp_commit();             // one group per phase (2 bufs)

        {
            const float* tbB = tiles + ((n0 + 1) % 6) * TSZ + rowbase;
            const ulonglong2* wbB = reinterpret_cast<const ulonglong2*>(&wsh[(n0 + 1) * 36]);
            compute_iter(n0,     tiles + (n0 % 6) * TSZ + rowbase, wA0, wA1, wA2);
            compute_iter(n0 + 1, tbB, wbB[0], wbB[1], wbB[2]);
        }
    }

    // ---- epilogue
    const float invn = 1.0f / 9.0f;
    size_t ob = ((((size_t)(b * 4) * 6 + c) * 6 + t) * 8 + d) * (size_t)HW_PLANE;
    const size_t ostride = (size_t)6 * 6 * 8 * HW_PLANE;

    #pragma unroll
    for (int py = 0; py < 2; py++) {
        int h = h0 + ty * 2 + py;
        size_t rowoff = ob + (size_t)h * 96 + tx * 4;
        float v0[4], v1[4], v2[4], v3[4];
        #pragma unroll
        for (int px = 0; px < 4; px++) {
            float2 p01 = unpack2(a01[py][px]);
            float2 p23 = unpack2(a23[py][px]);
            v0[px] = p01.x; v1[px] = p01.y; v2[px] = p23.x; v3[px] = p23.y;
        }
        float4 w4;
        w4 = make_float4(fmaf(v0[0], invn, mbsh[0]), fmaf(v0[1], invn, mbsh[0]),
                         fmaf(v0[2], invn, mbsh[0]), fmaf(v0[3], invn, mbsh[0]));
        *reinterpret_cast<float4*>(out + rowoff) = w4;
        w4 = make_float4(fmaf(v1[0], invn, mbsh[1]), fmaf(v1[1], invn, mbsh[1]),
                         fmaf(v1[2], invn, mbsh[1]), fmaf(v1[3], invn, mbsh[1]));
        *reinterpret_cast<float4*>(out + rowoff + ostride) = w4;
        w4 = make_float4(fmaf(v2[0], invn, mbsh[2]), fmaf(v2[1], invn, mbsh[2]),
                         fmaf(v2[2], invn, mbsh[2]), fmaf(v2[3], invn, mbsh[2]));
        *reinterpret_cast<float4*>(out + rowoff + 2 * ostride) = w4;
        w4 = make_float4(fmaf(v3[0], invn, mbsh[3]), fmaf(v3[1], invn, mbsh[3]),
                         fmaf(v3[2], invn, mbsh[3]), fmaf(v3[3], invn, mbsh[3]));
        *reinterpret_cast<float4*>(out + rowoff + 3 * ostride) = w4;
    }
}

extern "C" void kernel_launch(void* const* d_in, const int* in_sizes, int n_in,
                              void* d_out, int out_size) {
    const float* x  = (const float*)d_in[0];
    const float* Wg = (const float*)d_in[1];
    const float* bg = (const float*)d_in[2];
    float* out = (float*)d_out;

    const int dynsmem = 6 * TSZ * (int)sizeof(float);   // 6 input-plane buffers
    cudaFuncSetAttribute(conv5d_kernel, cudaFuncAttributeMaxDynamicSharedMemorySize, dynsmem);

    dim3 grid(24, 6, 12);   // x: htile(3) + 3*d(8); y: t(6); z: b*6+c(12)
    dim3 block(384);
    conv5d_kernel<<<grid, block, dynsmem>>>(x, Wg, bg, out);
}

// round 6
// speedup vs baseline: 1.0189x; 1.0189x over previous
#include <cuda_runtime.h>
#include <cstdint>

// x: [2][4][8][8][8][96][96] f32, W: [9][4][4][3][3][3] f32, b: [9][4] f32
// out: [2][4][6][6][8][96][96] f32
#define HW_PLANE 9216
#define TSTRIDE  104                 // floats per slab row: [pad3][w-1@3][w0..95@4..99][w96@100][pad]
#define SLOTF    (4 * TSTRIDE)       // floats per slot (4 rows)
typedef unsigned long long u64;

__device__ __forceinline__ void cp_async16(uint32_t saddr, const void* g, int srcsize) {
    asm volatile("cp.async.cg.shared.global [%0], [%1], 16, %2;\n"
                 :: "r"(saddr), "l"(g), "r"(srcsize));
}
__device__ __forceinline__ void cp_commit() {
    asm volatile("cp.async.commit_group;\n" ::: "memory");
}
__device__ __forceinline__ void cp_wait2() {
    asm volatile("cp.async.wait_group 2;\n" ::: "memory");
}
__device__ __forceinline__ u64 pack2(float lo, float hi) {
    u64 r; asm("mov.b64 %0, {%1, %2};" : "=l"(r) : "f"(lo), "f"(hi)); return r;
}
__device__ __forceinline__ void ffma2(u64& a, u64 x, u64 w) {
    asm("fma.rn.f32x2 %0, %1, %2, %0;" : "+l"(a) : "l"(x), "l"(w));
}
__device__ __forceinline__ float2 unpack2(u64 v) {
    float lo, hi; asm("mov.b64 {%0, %1}, %2;" : "=f"(lo), "=f"(hi) : "l"(v));
    return make_float2(lo, hi);
}

// Block: 256 threads = 8 warps. Warp = 2 output rows x 96 cols (lane: 3 cols), 4 o-chans.
// Tile: 16 rows per block. 108 iters = ci(4) x ij(9) x kd(3).
// Per-warp private slabs: 4 slots x (4 rows x 104 floats). NO block barrier in main loop —
// each warp self-paces on its own cp.async groups + __syncwarp. 3 blocks/SM.
__global__ __launch_bounds__(256, 3)
void conv5d_kernel(const float* __restrict__ x,
                   const float* __restrict__ Wg,
                   const float* __restrict__ bg,
                   float* __restrict__ out)
{
    extern __shared__ __align__(16) float tiles[];     // [8 warps][4 slots][SLOTF]
    __shared__ __align__(16) float wsh[3888];          // [n(108)][tap(9)][o(4)]
    __shared__ float mbsh[4];

    const int tid   = threadIdx.x;
    const int warp  = tid >> 5;
    const int lane  = tid & 31;
    const int htile = blockIdx.x % 6;
    const int d     = blockIdx.x / 6;
    const int t     = blockIdx.y;
    const int c     = blockIdx.z % 6;
    const int b     = blockIdx.z / 6;
    const int h0    = htile * 16;

    // ---- stage weights: wsh[n*36 + tap*4 + o], n = (ci*9+ij)*3+kd
    for (int idx = tid; idx < 3888; idx += 256) {
        int o   = idx & 3;
        int tap = (idx >> 2) % 9;
        int kd  = (idx / 36) % 3;
        int ij  = (idx / 108) % 9;
        int ci  = idx / 972;
        int kh = tap / 3, kw = tap - kh * 3;
        wsh[idx] = Wg[((ij * 4 + o) * 4 + ci) * 27 + kd * 9 + kh * 3 + kw];
    }
    if (tid < 4) {
        float s = 0.f;
        #pragma unroll
        for (int ij = 0; ij < 9; ij++) s += bg[ij * 4 + tid];
        mbsh[tid] = s * (1.0f / 9.0f);
    }

    float* slab = tiles + warp * (4 * SLOTF);
    // halo columns (w=-1, w=96) are conv zero padding: zero once per slot row (32 cells/warp)
    {
        int slot = lane >> 3, row = (lane >> 1) & 3, side = lane & 1;
        slab[slot * SLOTF + row * TSTRIDE + (side ? 100 : 3)] = 0.f;
    }

    // ---- per-lane cp.async chunks: 4 rows x 24 chunks(16B) = 96 = 32 lanes x 3
    int cso[3], cgo[3], csz[3];
    #pragma unroll
    for (int e = 0; e < 3; e++) {
        int chunk = lane + 32 * e;
        int row = chunk / 24;
        int col = chunk - row * 24;
        int h = h0 + 2 * warp - 1 + row;       // rows 2w-1 .. 2w+2 of the block tile
        bool hv = (h >= 0 && h < 96);
        cso[e] = row * TSTRIDE + 4 + col * 4;
        cgo[e] = (hv ? h : 0) * 96 + col * 4;
        csz[e] = hv ? 16 : 0;
    }
    uint32_t sbslot[4];
    #pragma unroll
    for (int s = 0; s < 4; s++)
        sbslot[s] = (uint32_t)__cvta_generic_to_shared(slab + s * SLOTF);

    // ---- issue-side state machine over (ci, i, j, kd)
    const float* xb = x + (size_t)b * (4 * 8 * 8 * 8 * HW_PLANE);
    const float* bcur = xb + ((size_t)((c * 8 + t) * 8) + (d - 1)) * HW_PLANE;
    int kd_m = 0, jj = 0, ii = 0;
    const bool dval0 = (d >= 1), dval2 = (d <= 6);

    auto issue_slot = [&](int s) {
        bool dv = (kd_m == 0) ? dval0 : ((kd_m == 2) ? dval2 : true);
        const float* plane = dv ? (bcur + (size_t)kd_m * HW_PLANE) : (bcur + HW_PLANE);
        uint32_t sbase = sbslot[s];
        #pragma unroll
        for (int e = 0; e < 3; e++)
            cp_async16(sbase + (uint32_t)cso[e] * 4u, plane + cgo[e], dv ? csz[e] : 0);
        kd_m++;
        if (kd_m == 3) {
            kd_m = 0;
            long step = 8;                      // j++
            jj++;
            if (jj == 3) { jj = 0; ii++; step = 48;          // i++
                if (ii == 3) { ii = 0; step = 368; } }       // ci++
            bcur += step * (long)HW_PLANE;
        }
    };

    __syncthreads();     // wsh ready (single barrier; none in the main loop)

    // accumulators: (o0,o1) and (o2,o3) pairs, [py][px], px = 0..2
    u64 a01[2][3], a23[2][3];
    #pragma unroll
    for (int py = 0; py < 2; py++)
        #pragma unroll
        for (int px = 0; px < 3; px++) { a01[py][px] = 0ull; a23[py][px] = 0ull; }

    // load one slab row -> 5 duplicated f32x2 values (conflict-free: bank stride 3)
    auto loadrow = [&](const float* rw, u64* p) {
        #pragma unroll
        for (int k = 0; k < 5; k++) { float v = rw[k]; p[k] = pack2(v, v); }
    };
    // one kh tap-row applied to two output rows (py0 from p0, py1 from p1)
    auto fmakh = [&](const u64* p0, const u64* p1,
                     ulonglong2 w0, ulonglong2 w1, ulonglong2 w2) {
        #pragma unroll
        for (int px = 0; px < 3; px++) {
            ffma2(a01[0][px], p0[px],     w0.x); ffma2(a23[0][px], p0[px],     w0.y);
            ffma2(a01[1][px], p1[px],     w0.x); ffma2(a23[1][px], p1[px],     w0.y);
            ffma2(a01[0][px], p0[px + 1], w1.x); ffma2(a23[0][px], p0[px + 1], w1.y);
            ffma2(a01[1][px], p1[px + 1], w1.x); ffma2(a23[1][px], p1[px + 1], w1.y);
            ffma2(a01[0][px], p0[px + 2], w2.x); ffma2(a23[0][px], p0[px + 2], w2.y);
            ffma2(a01[1][px], p1[px + 2], w2.x); ffma2(a23[1][px], p1[px + 2], w2.y);
        }
    };

    // prologue: 3 groups (slots 0..2) in flight
    issue_slot(0); cp_commit();
    issue_slot(1); cp_commit();
    issue_slot(2); cp_commit();

    const float* lanebase = slab + 3 + 3 * lane;

    for (int n = 0; n < 108; n++) {
        cp_wait2();          // own groups: <=2 outstanding -> group n landed
        __syncwarp();        // publish all lanes' copies of slot n; fence slot (n+3)&3 reads
        if (n + 3 < 108) issue_slot((n + 3) & 3);
        cp_commit();

        const float* tb = lanebase + (n & 3) * SLOTF;
        const ulonglong2* wb = reinterpret_cast<const ulonglong2*>(&wsh[n * 36]);
        u64 pa[5], pb[5];
        loadrow(tb,               pa);          // row 0
        loadrow(tb + TSTRIDE,     pb);          // row 1
        fmakh(pa, pb, wb[0], wb[1], wb[2]);     // kh = 0
        loadrow(tb + 2 * TSTRIDE, pa);          // row 2
        fmakh(pb, pa, wb[3], wb[4], wb[5]);     // kh = 1
        loadrow(tb + 3 * TSTRIDE, pb);          // row 3
        fmakh(pa, pb, wb[6], wb[7], wb[8]);     // kh = 2
    }

    // ---- epilogue: out[b][o][c][t][d][h][w]
    const float invn = 1.0f / 9.0f;
    const float mb0 = mbsh[0], mb1 = mbsh[1], mb2 = mbsh[2], mb3 = mbsh[3];
    size_t ob = ((((size_t)(b * 4) * 6 + c) * 6 + t) * 8 + d) * (size_t)HW_PLANE;
    const size_t ostride = (size_t)6 * 6 * 8 * HW_PLANE;

    #pragma unroll
    for (int py = 0; py < 2; py++) {
        int h = h0 + 2 * warp + py;
        size_t rowoff = ob + (size_t)h * 96 + 3 * lane;
        #pragma unroll
        for (int px = 0; px < 3; px++) {
            float2 q01 = unpack2(a01[py][px]);
            float2 q23 = unpack2(a23[py][px]);
            out[rowoff + px]               = fmaf(q01.x, invn, mb0);
            out[rowoff + ostride + px]     = fmaf(q01.y, invn, mb1);
            out[rowoff + 2 * ostride + px] = fmaf(q23.x, invn, mb2);
            out[rowoff + 3 * ostride + px] = fmaf(q23.y, invn, mb3);
        }
    }
}

extern "C" void kernel_launch(void* const* d_in, const int* in_sizes, int n_in,
                              void* d_out, int out_size) {
    const float* x  = (const float*)d_in[0];
    const float* Wg = (const float*)d_in[1];
    const float* bg = (const float*)d_in[2];
    float* out = (float*)d_out;

    const int dynsmem = 8 * 4 * SLOTF * (int)sizeof(float);   // 8 warps x 4 slots
    cudaFuncSetAttribute(conv5d_kernel, cudaFuncAttributeMaxDynamicSharedMemorySize, dynsmem);

    dim3 grid(48, 6, 12);   // x: htile(6) + 6*d(8); y: t(6); z: b*6+c(12)
    dim3 block(256);
    conv5d_kernel<<<grid, block, dynsmem>>>(x, Wg, bg, out);
}

// round 7
// speedup vs baseline: 1.0424x; 1.0230x over previous
#include <cuda_runtime.h>
#include <cstdint>

// x: [2][4][8][8][8][96][96] f32, W: [9][4][4][3][3][3] f32, b: [9][4] f32
// out: [2][4][6][6][8][96][96] f32
#define HW_PLANE 9216
#define TSTRIDE  104                 // floats per slab row: [pad3][w-1@3][w0..95][w96@100][pad]
#define SLOTF    (4 * TSTRIDE)       // floats per slot (4 rows) = 416
typedef unsigned long long u64;

__device__ __forceinline__ void cp_async16(uint32_t saddr, const void* g, int srcsize) {
    asm volatile("cp.async.cg.shared.global [%0], [%1], 16, %2;\n"
                 :: "r"(saddr), "l"(g), "r"(srcsize));
}
__device__ __forceinline__ void cp_commit() {
    asm volatile("cp.async.commit_group;\n" ::: "memory");
}
__device__ __forceinline__ void cp_wait1() {
    asm volatile("cp.async.wait_group 1;\n" ::: "memory");
}
__device__ __forceinline__ u64 pack2(float lo, float hi) {
    u64 r; asm("mov.b64 %0, {%1, %2};" : "=l"(r) : "f"(lo), "f"(hi)); return r;
}
__device__ __forceinline__ void ffma2(u64& a, u64 x, u64 w) {
    asm("fma.rn.f32x2 %0, %1, %2, %0;" : "+l"(a) : "l"(x), "l"(w));
}
__device__ __forceinline__ float2 unpack2(u64 v) {
    float lo, hi; asm("mov.b64 {%0, %1}, %2;" : "=f"(lo), "=f"(hi) : "l"(v));
    return make_float2(lo, hi);
}

// Block: 256 threads = 8 warps. Warp = 2 output rows x 96 cols (lane: 3 cols), 4 o-chans.
// 108 iters = 36 macro-iters (ci,i,j) x kd(0,1,2) fully static inner. Per-warp private
// slabs: 3 slots x (4 rows x 104 floats); warp self-paced (no block barrier in loop).
// Target 4 blocks/SM (64 regs).
__global__ __launch_bounds__(256, 4)
void conv5d_kernel(const float* __restrict__ x,
                   const float* __restrict__ Wg,
                   const float* __restrict__ bg,
                   float* __restrict__ out)
{
    extern __shared__ __align__(16) float tiles[];     // [8 warps][3 slots][SLOTF]
    __shared__ __align__(16) float wsh[3888];          // [n(108)][tap(9)][o(4)]
    __shared__ float mbsh[4];

    const int tid   = threadIdx.x;
    const int warp  = tid >> 5;
    const int lane  = tid & 31;
    const int htile = blockIdx.x % 6;
    const int d     = blockIdx.x / 6;
    const int t     = blockIdx.y;
    const int c     = blockIdx.z % 6;
    const int b     = blockIdx.z / 6;
    const int h0    = htile * 16;

    // ---- stage weights: wsh[n*36 + tap*4 + o], n = (ci*9+ij)*3+kd
    for (int idx = tid; idx < 3888; idx += 256) {
        int o   = idx & 3;
        int tap = (idx >> 2) % 9;
        int kd  = (idx / 36) % 3;
        int ij  = (idx / 108) % 9;
        int ci  = idx / 972;
        int kh = tap / 3, kw = tap - kh * 3;
        wsh[idx] = Wg[((ij * 4 + o) * 4 + ci) * 27 + kd * 9 + kh * 3 + kw];
    }
    if (tid < 4) {
        float s = 0.f;
        #pragma unroll
        for (int ij = 0; ij < 9; ij++) s += bg[ij * 4 + tid];
        mbsh[tid] = s * (1.0f / 9.0f);
    }

    float* slab = tiles + warp * (3 * SLOTF);
    // halo columns (w=-1, w=96) are conv zero padding: zero once per slot row (24 cells/warp)
    if (lane < 24) {
        int slot = lane / 8, row = (lane >> 1) & 3, side = lane & 1;
        slab[slot * SLOTF + row * TSTRIDE + (side ? 100 : 3)] = 0.f;
    }

    // ---- per-lane cp.async chunk descriptors, packed: [0:10) smem fidx, [10:24) gmem fidx, [24] valid
    uint32_t pk[3];
    #pragma unroll
    for (int e = 0; e < 3; e++) {
        int chunk = lane + 32 * e;
        int row = chunk / 24;
        int col = chunk - row * 24;
        int h = h0 + 2 * warp - 1 + row;       // rows 2w-1 .. 2w+2 of the block tile
        bool hv = (h >= 0 && h < 96);
        uint32_t so = (uint32_t)(row * TSTRIDE + 4 + col * 4);
        uint32_t go = (uint32_t)((hv ? h : 0) * 96 + col * 4);
        pk[e] = so | (go << 10) | (hv ? (1u << 24) : 0u);
    }
    const uint32_t sbase = (uint32_t)__cvta_generic_to_shared(slab);

    auto issue = [&](uint32_t sslot, const float* plane, bool dv) {
        #pragma unroll
        for (int e = 0; e < 3; e++) {
            uint32_t p  = pk[e];
            uint32_t so = p & 1023u;
            uint32_t go = (p >> 10) & 16383u;
            int sz = (dv && (p >> 24)) ? 16 : 0;
            cp_async16(sslot + so * 4u, plane + go, sz);
        }
    };

    // accumulators: (o0,o1) and (o2,o3) pairs, [py][px], px = 0..2
    u64 a01[2][3], a23[2][3];
    #pragma unroll
    for (int py = 0; py < 2; py++)
        #pragma unroll
        for (int px = 0; px < 3; px++) { a01[py][px] = 0ull; a23[py][px] = 0ull; }

    auto loadrow = [&](const float* rw, u64* p) {
        #pragma unroll
        for (int k = 0; k < 5; k++) { float v = rw[k]; p[k] = pack2(v, v); }
    };
    auto fmakh = [&](const u64* p0, const u64* p1,
                     ulonglong2 w0, ulonglong2 w1, ulonglong2 w2) {
        #pragma unroll
        for (int px = 0; px < 3; px++) {
            ffma2(a01[0][px], p0[px],     w0.x); ffma2(a23[0][px], p0[px],     w0.y);
            ffma2(a01[1][px], p1[px],     w0.x); ffma2(a23[1][px], p1[px],     w0.y);
            ffma2(a01[0][px], p0[px + 1], w1.x); ffma2(a23[0][px], p0[px + 1], w1.y);
            ffma2(a01[1][px], p1[px + 1], w1.x); ffma2(a23[1][px], p1[px + 1], w1.y);
            ffma2(a01[0][px], p0[px + 2], w2.x); ffma2(a23[0][px], p0[px + 2], w2.y);
            ffma2(a01[1][px], p1[px + 2], w2.x); ffma2(a23[1][px], p1[px + 2], w2.y);
        }
    };
    auto compute = [&](int n, const float* tb) {
        const ulonglong2* wb = reinterpret_cast<const ulonglong2*>(&wsh[n * 36]);
        u64 pa[5], pb[5];
        loadrow(tb,               pa);
        loadrow(tb + TSTRIDE,     pb);
        fmakh(pa, pb, wb[0], wb[1], wb[2]);
        loadrow(tb + 2 * TSTRIDE, pa);
        fmakh(pb, pa, wb[3], wb[4], wb[5]);
        loadrow(tb + 3 * TSTRIDE, pb);
        fmakh(pa, pb, wb[6], wb[7], wb[8]);
    };

    const bool dval0 = (d >= 1), dval2 = (d <= 6);
    const float* bm = x + (size_t)b * (4 * 8 * 8 * 8 * HW_PLANE)
                    + ((size_t)((c * 8 + t) * 8) + (d - 1)) * HW_PLANE;  // macro-0 base (dz=d-1)

    // prologue: n=0 (kd'=0, slot0), n=1 (kd'=1, slot1)
    issue(sbase,                 dval0 ? bm : bm + HW_PLANE, dval0); cp_commit();
    issue(sbase + SLOTF * 4,     bm + HW_PLANE,              true);  cp_commit();

    __syncthreads();     // wsh/mbsh ready; no block barrier beyond this point

    const float* lanebase = slab + 3 + 3 * lane;
    int n = 0;           // iteration counter (for weight indexing)

    #pragma unroll 1
    for (int ci = 0; ci < 4; ci++) {
        #pragma unroll 1
        for (int i = 0; i < 3; i++) {
            #pragma unroll
            for (int j = 0; j < 3; j++) {
                const bool last = (ci == 3) && (i == 2) && (j == 2);
                // next macro base
                const float* bn = bm + (size_t)((j < 2) ? 8 : ((i < 2) ? 48 : 368)) * HW_PLANE;

                // ---- kd = 0: compute slot0, issue n+2 -> (macro m, kd'=2) slot2
                cp_wait1(); __syncwarp();
                issue(sbase + 2 * SLOTF * 4, dval2 ? bm + 2 * HW_PLANE : bm + HW_PLANE, dval2);
                cp_commit();
                compute(n, lanebase);

                // ---- kd = 1: compute slot1, issue n+3 -> (macro m+1, kd'=0) slot0
                cp_wait1(); __syncwarp();
                if (!last) issue(sbase, dval0 ? bn : bn + HW_PLANE, dval0);
                cp_commit();
                compute(n + 1, lanebase + SLOTF);

                // ---- kd = 2: compute slot2, issue n+4 -> (macro m+1, kd'=1) slot1
                cp_wait1(); __syncwarp();
                if (!last) issue(sbase + SLOTF * 4, bn + HW_PLANE, true);
                cp_commit();
                compute(n + 2, lanebase + 2 * SLOTF);

                n += 3;
                bm = bn;
            }
        }
    }

    // ---- epilogue: out[b][o][c][t][d][h][w]
    const float invn = 1.0f / 9.0f;
    const float mb0 = mbsh[0], mb1 = mbsh[1], mb2 = mbsh[2], mb3 = mbsh[3];
    size_t ob = ((((size_t)(b * 4) * 6 + c) * 6 + t) * 8 + d) * (size_t)HW_PLANE;
    const size_t ostride = (size_t)6 * 6 * 8 * HW_PLANE;

    #pragma unroll
    for (int py = 0; py < 2; py++) {
        int h = h0 + 2 * warp + py;
        size_t rowoff = ob + (size_t)h * 96 + 3 * lane;
        #pragma unroll
        for (int px = 0; px < 3; px++) {
            float2 q01 = unpack2(a01[py][px]);
            float2 q23 = unpack2(a23[py][px]);
            out[rowoff + px]               = fmaf(q01.x, invn, mb0);
            out[rowoff + ostride + px]     = fmaf(q01.y, invn, mb1);
            out[rowoff + 2 * ostride + px] = fmaf(q23.x, invn, mb2);
            out[rowoff + 3 * ostride + px] = fmaf(q23.y, invn, mb3);
        }
    }
}

extern "C" void kernel_launch(void* const* d_in, const int* in_sizes, int n_in,
                              void* d_out, int out_size) {
    const float* x  = (const float*)d_in[0];
    const float* Wg = (const float*)d_in[1];
    const float* bg = (const float*)d_in[2];
    float* out = (float*)d_out;

    const int dynsmem = 8 * 3 * SLOTF * (int)sizeof(float);   // 8 warps x 3 slots = 39936 B
    cudaFuncSetAttribute(conv5d_kernel, cudaFuncAttributeMaxDynamicSharedMemorySize, dynsmem);

    dim3 grid(48, 6, 12);   // x: htile(6) + 6*d(8); y: t(6); z: b*6+c(12)
    dim3 block(256);
    conv5d_kernel<<<grid, block, dynsmem>>>(x, Wg, bg, out);
}